// round 3
// baseline (speedup 1.0000x reference)
#include <cuda_runtime.h>
#include <cuda_fp16.h>
#include <cstdint>

#define SEQ    8192
#define VOCAB  256
#define HID    2048
#define OUTN   256

#define NCTA     148
#define NTHREADS 224          // 7 warps, 2 units each
#define MAX_SMEM_DOTS 54      // 54 * 4096 B weights + 8192 B h = 229376 <= 232448
#define SMEM_RECUR (MAX_SMEM_DOTS * HID * 2 + HID * 4)

// ---------------- device scratch (module-scope: no runtime allocs) ----------------
__device__ __half d_Uh[(size_t)4 * HID * HID];     // 33.5 MB  [(j*4+g)*HID + k] = U_g[k][j]
__device__ float  d_G[(size_t)4 * VOCAB * HID];    // 8 MB     [((v*HID)+j)*4 + g] = emb[v]@W_g + b_g + c_g
__device__ float  d_hs[(size_t)SEQ * HID];         // 67 MB    h history for output GEMM
__device__ float  d_hbuf[2][HID];                  // double-buffered cross-CTA h
__device__ float  d_cfinal[HID];
__device__ unsigned d_barcnt;
__device__ unsigned d_bargen;

struct GateArgs {
    const float* W[4];
    const float* b[4];
    const float* cb[4];
};
struct UArgs {
    const float* U[4];
};

// ============================================================================
// Kernel 1: gate tables  G[v][j][g] = sum_k emb[v][k]*W_g[k][j] + b_g[j] + c_g[j]
// grid (32, 4) x 256 threads; each block: 8 vocab rows, one gate
// ============================================================================
__global__ void __launch_bounds__(256) prep_tables_kernel(const float* __restrict__ emb, GateArgs ga)
{
    const int g  = blockIdx.y;
    const float* __restrict__ W  = ga.W[g];
    const float* __restrict__ b  = ga.b[g];
    const float* __restrict__ cb = ga.cb[g];
    const int v0 = blockIdx.x * 8;
    const int tid = threadIdx.x;

    __shared__ float es[8 * 256];
    for (int i = tid; i < 8 * 256; i += 256)
        es[i] = emb[(size_t)(v0 + (i >> 8)) * VOCAB + (i & 255)];
    __syncthreads();

    for (int jj = 0; jj < 8; jj++) {
        const int j = tid + (jj << 8);
        float acc[8];
        #pragma unroll
        for (int v = 0; v < 8; v++) acc[v] = 0.f;
        #pragma unroll 4
        for (int k = 0; k < 256; k++) {
            const float wv = W[(size_t)k * HID + j];
            #pragma unroll
            for (int v = 0; v < 8; v++)
                acc[v] = fmaf(es[(v << 8) + k], wv, acc[v]);
        }
        const float bias = b[j] + cb[j];
        #pragma unroll
        for (int v = 0; v < 8; v++)
            d_G[(((size_t)(v0 + v) * HID) + j) * 4 + g] = acc[v] + bias;
    }
}

// ============================================================================
// Kernel 2: transpose + fp16-convert U:  d_Uh[(j*4+g)*HID + k] = half(U_g[k][j])
// grid (64, 64, 4) x (32,32)
// ============================================================================
__global__ void __launch_bounds__(1024) prep_weights_kernel(UArgs ua)
{
    const int g = blockIdx.z;
    const float* __restrict__ U = ua.U[g];
    __shared__ float tile[32][33];
    const int j0 = blockIdx.x * 32;
    const int k0 = blockIdx.y * 32;
    const int tx = threadIdx.x, ty = threadIdx.y;

    tile[ty][tx] = U[(size_t)(k0 + ty) * HID + (j0 + tx)];
    __syncthreads();
    d_Uh[((size_t)(j0 + ty) * 4 + g) * HID + (k0 + tx)] = __float2half(tile[tx][ty]);
}

// ============================================================================
// Kernel 3: persistent recurrence. 148 CTAs (1/SM), weight-resident in SMEM.
// ============================================================================
__device__ __forceinline__ float sigmoid_f(float z)
{
    return 1.f / (1.f + __expf(-z));
}
__device__ __forceinline__ float tanh_f(float z)
{
    // 1 - 2/(exp(2z)+1): exact limits at +/-inf, ~2^-21 rel err elsewhere
    const float e = __expf(2.f * z);
    return 1.f - __fdividef(2.f, 1.f + e);
}

__global__ void __launch_bounds__(NTHREADS, 1) lstm_recur_kernel(const int* __restrict__ x)
{
    extern __shared__ char smem_raw[];
    float* __restrict__ h_sm = (float*)(smem_raw + MAX_SMEM_DOTS * HID * 2);
    float2* __restrict__ h2  = (float2*)h_sm;

    const int cta  = blockIdx.x;
    const int tid  = threadIdx.x;
    const int lane = tid & 31;
    const int w    = tid >> 5;

    // unit partition: first 124 CTAs own 14 units, last 24 own 13 (124*14+24*13 = 2048)
    const int nu = (cta < 124) ? 14 : 13;
    const int u0 = (cta < 124) ? cta * 14 : 1736 + (cta - 124) * 13;
    const int nd = nu * 4;
    const int nds = (nd < MAX_SMEM_DOTS) ? nd : MAX_SMEM_DOTS;

    // stage this CTA's weight block (contiguous in d_Uh) into SMEM
    {
        const uint4* __restrict__ src = (const uint4*)(d_Uh + (size_t)u0 * 4 * HID);
        uint4* __restrict__ dst = (uint4*)smem_raw;
        const int n = nds * (HID / 8);
        for (int i = tid; i < n; i += NTHREADS) dst[i] = src[i];
    }
    for (int i = tid; i < HID; i += NTHREADS) h_sm[i] = 0.f;

    // per-warp setup: units 2w, 2w+1
    const int lu0 = 2 * w;
    const int myu = (lu0 + 1 < nu) ? 2 : ((lu0 < nu) ? 1 : 0);
    const __half2* pw[8];
    #pragma unroll
    for (int d = 0; d < 8; d++) pw[d] = (const __half2*)smem_raw;  // safe default
    for (int uu = 0; uu < myu; uu++) {
        for (int g = 0; g < 4; g++) {
            const int ld = (lu0 + uu) * 4 + g;
            if (ld < nds)
                pw[uu * 4 + g] = ((const __half2*)smem_raw) + (size_t)ld * (HID / 2);
            else
                pw[uu * 4 + g] = (const __half2*)(d_Uh + ((size_t)(u0 + lu0 + uu) * 4 + g) * HID);
        }
    }

    float cst0 = 0.f, cst1 = 0.f;
    unsigned mygen = 0;
    if (tid == 0) mygen = *((volatile unsigned*)&d_bargen);
    __syncthreads();

    for (int t = 0; t < SEQ; t++) {
        // prefetch gate-table row early (L2 latency hidden under dot loop)
        float4 gz0 = make_float4(0.f, 0.f, 0.f, 0.f);
        float4 gz1 = make_float4(0.f, 0.f, 0.f, 0.f);
        if (myu) {
            const int xt = __ldg(&x[t]);
            const float4* Gp = ((const float4*)d_G) + (size_t)xt * HID + (u0 + lu0);
            gz0 = __ldg(&Gp[0]);
            if (myu == 2) gz1 = __ldg(&Gp[1]);
        }

        // dots: z[d] = h . U_row(d)
        float2 a0 = {0.f,0.f}, a1 = {0.f,0.f}, a2 = {0.f,0.f}, a3 = {0.f,0.f};
        float2 a4 = {0.f,0.f}, a5 = {0.f,0.f}, a6 = {0.f,0.f}, a7 = {0.f,0.f};
        if (myu == 2) {
            #pragma unroll 4
            for (int ii = 0; ii < 32; ii++) {
                const int i = lane + (ii << 5);
                const float2 hv = h2[i];
                float2 wf;
                wf = __half22float2(pw[0][i]); a0.x = fmaf(hv.x, wf.x, a0.x); a0.y = fmaf(hv.y, wf.y, a0.y);
                wf = __half22float2(pw[1][i]); a1.x = fmaf(hv.x, wf.x, a1.x); a1.y = fmaf(hv.y, wf.y, a1.y);
                wf = __half22float2(pw[2][i]); a2.x = fmaf(hv.x, wf.x, a2.x); a2.y = fmaf(hv.y, wf.y, a2.y);
                wf = __half22float2(pw[3][i]); a3.x = fmaf(hv.x, wf.x, a3.x); a3.y = fmaf(hv.y, wf.y, a3.y);
                wf = __half22float2(pw[4][i]); a4.x = fmaf(hv.x, wf.x, a4.x); a4.y = fmaf(hv.y, wf.y, a4.y);
                wf = __half22float2(pw[5][i]); a5.x = fmaf(hv.x, wf.x, a5.x); a5.y = fmaf(hv.y, wf.y, a5.y);
                wf = __half22float2(pw[6][i]); a6.x = fmaf(hv.x, wf.x, a6.x); a6.y = fmaf(hv.y, wf.y, a6.y);
                wf = __half22float2(pw[7][i]); a7.x = fmaf(hv.x, wf.x, a7.x); a7.y = fmaf(hv.y, wf.y, a7.y);
            }
        } else if (myu == 1) {
            #pragma unroll 4
            for (int ii = 0; ii < 32; ii++) {
                const int i = lane + (ii << 5);
                const float2 hv = h2[i];
                float2 wf;
                wf = __half22float2(pw[0][i]); a0.x = fmaf(hv.x, wf.x, a0.x); a0.y = fmaf(hv.y, wf.y, a0.y);
                wf = __half22float2(pw[1][i]); a1.x = fmaf(hv.x, wf.x, a1.x); a1.y = fmaf(hv.y, wf.y, a1.y);
                wf = __half22float2(pw[2][i]); a2.x = fmaf(hv.x, wf.x, a2.x); a2.y = fmaf(hv.y, wf.y, a2.y);
                wf = __half22float2(pw[3][i]); a3.x = fmaf(hv.x, wf.x, a3.x); a3.y = fmaf(hv.y, wf.y, a3.y);
            }
        }

        float z[8];
        z[0] = a0.x + a0.y; z[1] = a1.x + a1.y; z[2] = a2.x + a2.y; z[3] = a3.x + a3.y;
        z[4] = a4.x + a4.y; z[5] = a5.x + a5.y; z[6] = a6.x + a6.y; z[7] = a7.x + a7.y;
        #pragma unroll
        for (int d = 0; d < 8; d++) {
            float s = z[d];
            #pragma unroll
            for (int off = 16; off > 0; off >>= 1)
                s += __shfl_xor_sync(0xffffffffu, s, off);
            z[d] = s;
        }

        // gates + cell update (replicated across lanes; lane 0 stores)
        if (myu) {
            {
                const float ig = sigmoid_f(z[0] + gz0.x);
                const float fg = sigmoid_f(z[1] + gz0.y);
                const float gg = tanh_f   (z[2] + gz0.z);
                const float og = sigmoid_f(z[3] + gz0.w);
                const float cn = fg * cst0 + ig * gg;
                cst0 = cn;
                const float hn = og * tanh_f(cn);
                if (lane == 0) {
                    const int j = u0 + lu0;
                    d_hbuf[t & 1][j] = hn;
                    d_hs[(size_t)t * HID + j] = hn;
                    if (t == SEQ - 1) d_cfinal[j] = cn;
                }
            }
            if (myu == 2) {
                const float ig = sigmoid_f(z[4] + gz1.x);
                const float fg = sigmoid_f(z[5] + gz1.y);
                const float gg = tanh_f   (z[6] + gz1.z);
                const float og = sigmoid_f(z[7] + gz1.w);
                const float cn = fg * cst1 + ig * gg;
                cst1 = cn;
                const float hn = og * tanh_f(cn);
                if (lane == 0) {
                    const int j = u0 + lu0 + 1;
                    d_hbuf[t & 1][j] = hn;
                    d_hs[(size_t)t * HID + j] = hn;
                    if (t == SEQ - 1) d_cfinal[j] = cn;
                }
            }
        }

        // publish stores gpu-wide, then grid barrier
        if (lane == 0 && myu) __threadfence();
        __syncthreads();
        if (tid == 0) {
            const unsigned ticket = atomicAdd(&d_barcnt, 1u);
            if (ticket == gridDim.x - 1) {
                d_barcnt = 0;
                __threadfence();
                atomicAdd(&d_bargen, 1u);
            } else {
                while (*((volatile unsigned*)&d_bargen) == mygen) { }
            }
            __threadfence();
            mygen++;
        }
        __syncthreads();

        // gather the full new h into SMEM (L2, bypass L1)
        {
            float4* __restrict__ dst4 = (float4*)h_sm;
            const float4* __restrict__ s4 = (const float4*)d_hbuf[t & 1];
            for (int i = tid; i < HID / 4; i += NTHREADS)
                dst4[i] = __ldcg(&s4[i]);
        }
        __syncthreads();
    }
}

// ============================================================================
// Kernel 4: out = hs @ V_w + V_b   (8192x2048 @ 2048x256)
// 64x64 tiles, 256 threads, 4x4 per thread
// ============================================================================
__global__ void __launch_bounds__(256) out_gemm_kernel(const float* __restrict__ Vw,
                                                       const float* __restrict__ Vb,
                                                       float* __restrict__ out)
{
    __shared__ float As[16][64];
    __shared__ float Bs[16][64];
    const int tid = threadIdx.x;
    const int tx = tid & 15, ty = tid >> 4;
    const int m0 = blockIdx.x * 64, n0 = blockIdx.y * 64;

    float acc[4][4];
    #pragma unroll
    for (int i = 0; i < 4; i++)
        #pragma unroll
        for (int j = 0; j < 4; j++) acc[i][j] = 0.f;

    const int ar = tid >> 2, ac = (tid & 3) * 4;
    const int br = tid >> 4, bc = (tid & 15) * 4;

    for (int k0 = 0; k0 < HID; k0 += 16) {
        const float4 av = *(const float4*)&d_hs[(size_t)(m0 + ar) * HID + k0 + ac];
        As[ac + 0][ar] = av.x; As[ac + 1][ar] = av.y;
        As[ac + 2][ar] = av.z; As[ac + 3][ar] = av.w;
        *(float4*)&Bs[br][bc] = *(const float4*)&Vw[(size_t)(k0 + br) * OUTN + n0 + bc];
        __syncthreads();
        #pragma unroll
        for (int kk = 0; kk < 16; kk++) {
            float a4[4], b4[4];
            *(float4*)a4 = *(const float4*)&As[kk][ty * 4];
            *(float4*)b4 = *(const float4*)&Bs[kk][tx * 4];
            #pragma unroll
            for (int i = 0; i < 4; i++)
                #pragma unroll
                for (int j = 0; j < 4; j++)
                    acc[i][j] = fmaf(a4[i], b4[j], acc[i][j]);
        }
        __syncthreads();
    }
    #pragma unroll
    for (int i = 0; i < 4; i++) {
        #pragma unroll
        for (int j = 0; j < 4; j++) {
            const int oo = n0 + tx * 4 + j;
            out[(size_t)(m0 + ty * 4 + i) * OUTN + oo] = acc[i][j] + Vb[oo];
        }
    }
}

// ============================================================================
// Kernel 5: optional tail (h_T, c_T) if harness expects them appended
// ============================================================================
__global__ void tail_copy_kernel(float* __restrict__ out)
{
    const int i = blockIdx.x * blockDim.x + threadIdx.x;
    if (i < HID) {
        out[(size_t)SEQ * OUTN + i]       = d_hbuf[(SEQ - 1) & 1][i];
        out[(size_t)SEQ * OUTN + HID + i] = d_cfinal[i];
    }
}

// ============================================================================
// host launcher
// inputs: 0:x 1:emb 2:W_i 3:b_i 4:U_i 5:c_i 6:W_f 7:b_f 8:U_f 9:c_f
//         10:W_g 11:b_g 12:U_g 13:c_g 14:W_o 15:b_o 16:U_o 17:c_o 18:V_w 19:V_b
// ============================================================================
extern "C" void kernel_launch(void* const* d_in, const int* in_sizes, int n_in,
                              void* d_out, int out_size)
{
    const int*   x   = (const int*)d_in[0];
    const float* emb = (const float*)d_in[1];

    GateArgs ga;
    UArgs ua;
    // gate order: 0=i, 1=f, 2=g, 3=o
    ga.W[0] = (const float*)d_in[2];  ga.b[0] = (const float*)d_in[3];
    ua.U[0] = (const float*)d_in[4];  ga.cb[0] = (const float*)d_in[5];
    ga.W[1] = (const float*)d_in[6];  ga.b[1] = (const float*)d_in[7];
    ua.U[1] = (const float*)d_in[8];  ga.cb[1] = (const float*)d_in[9];
    ga.W[2] = (const float*)d_in[10]; ga.b[2] = (const float*)d_in[11];
    ua.U[2] = (const float*)d_in[12]; ga.cb[2] = (const float*)d_in[13];
    ga.W[3] = (const float*)d_in[14]; ga.b[3] = (const float*)d_in[15];
    ua.U[3] = (const float*)d_in[16]; ga.cb[3] = (const float*)d_in[17];
    const float* Vw = (const float*)d_in[18];
    const float* Vb = (const float*)d_in[19];
    float* out = (float*)d_out;

    cudaFuncSetAttribute(lstm_recur_kernel,
                         cudaFuncAttributeMaxDynamicSharedMemorySize, SMEM_RECUR);

    // 1) gate tables
    prep_tables_kernel<<<dim3(VOCAB / 8, 4), 256>>>(emb, ga);
    // 2) fp16 transposed recurrent weights
    prep_weights_kernel<<<dim3(HID / 32, HID / 32, 4), dim3(32, 32)>>>(ua);
    // 3) persistent recurrence
    lstm_recur_kernel<<<NCTA, NTHREADS, SMEM_RECUR>>>(x);
    // 4) output projection
    out_gemm_kernel<<<dim3(SEQ / 64, OUTN / 64), 256>>>(Vw, Vb, out);
    // 5) appended final states if requested
    if (out_size >= SEQ * OUTN + 2 * HID)
        tail_copy_kernel<<<(HID + 255) / 256, 256>>>(out);
}

// round 4
// speedup vs baseline: 1.2388x; 1.2388x over previous
#include <cuda_runtime.h>
#include <cuda_bf16.h>
#include <cstdint>

#define SEQ    8192
#define VOCAB  256
#define HID    2048
#define OUTN   256

#define NCTA     148
#define NTHREADS 224          // 7 warps, 2 units each
#define MAX_SMEM_DOTS 54      // 54 * 4096 B weights + 8192 B h = 229376 <= 232448
#define SMEM_RECUR (MAX_SMEM_DOTS * HID * 2 + HID * 4)

// ---------------- device scratch (module-scope: no runtime allocs) ----------------
__device__ __nv_bfloat16 d_Uh[(size_t)4 * HID * HID]; // 33.5 MB  [(j*4+g)*HID + k] = bf16(U_g[k][j])
__device__ float  d_G[(size_t)4 * VOCAB * HID];       // 8 MB     [(v*HID + j)*4 + g] = emb[v]@W_g + b_g + c_g
__device__ float  d_hs[(size_t)SEQ * HID];            // 67 MB    h history for output GEMM
__device__ float  d_hbuf[2][HID];                     // double-buffered cross-CTA h
__device__ float  d_cfinal[HID];
__device__ unsigned d_barcnt;
__device__ unsigned d_bargen;

struct GateArgs {
    const float* W[4];
    const float* b[4];
    const float* cb[4];
};
struct UArgs {
    const float* U[4];
};

// exact bf16 -> f32 (fixed-ALU ops, no F2F)
__device__ __forceinline__ float bf_lo(unsigned w) { return __uint_as_float(w << 16); }
__device__ __forceinline__ float bf_hi(unsigned w) { return __uint_as_float(w & 0xffff0000u); }

// ============================================================================
// Kernel 1: gate tables  G[v][j][g] = sum_k emb[v][k]*W_g[k][j] + b_g[j] + c_g[j]
// ============================================================================
__global__ void __launch_bounds__(256) prep_tables_kernel(const float* __restrict__ emb, GateArgs ga)
{
    const int g  = blockIdx.y;
    const float* __restrict__ W  = ga.W[g];
    const float* __restrict__ b  = ga.b[g];
    const float* __restrict__ cb = ga.cb[g];
    const int v0 = blockIdx.x * 8;
    const int tid = threadIdx.x;

    __shared__ float es[8 * 256];
    for (int i = tid; i < 8 * 256; i += 256)
        es[i] = emb[(size_t)(v0 + (i >> 8)) * VOCAB + (i & 255)];
    __syncthreads();

    for (int jj = 0; jj < 8; jj++) {
        const int j = tid + (jj << 8);
        float acc[8];
        #pragma unroll
        for (int v = 0; v < 8; v++) acc[v] = 0.f;
        #pragma unroll 4
        for (int k = 0; k < 256; k++) {
            const float wv = W[(size_t)k * HID + j];
            #pragma unroll
            for (int v = 0; v < 8; v++)
                acc[v] = fmaf(es[(v << 8) + k], wv, acc[v]);
        }
        const float bias = b[j] + cb[j];
        #pragma unroll
        for (int v = 0; v < 8; v++)
            d_G[(((size_t)(v0 + v) * HID) + j) * 4 + g] = acc[v] + bias;
    }
}

// ============================================================================
// Kernel 2: transpose + bf16-convert U:  d_Uh[(j*4+g)*HID + k] = bf16(U_g[k][j])
// ============================================================================
__global__ void __launch_bounds__(1024) prep_weights_kernel(UArgs ua)
{
    const int g = blockIdx.z;
    const float* __restrict__ U = ua.U[g];
    __shared__ float tile[32][33];
    const int j0 = blockIdx.x * 32;
    const int k0 = blockIdx.y * 32;
    const int tx = threadIdx.x, ty = threadIdx.y;

    tile[ty][tx] = U[(size_t)(k0 + ty) * HID + (j0 + tx)];
    __syncthreads();
    d_Uh[((size_t)(j0 + ty) * 4 + g) * HID + (k0 + tx)] = __float2bfloat16(tile[tx][ty]);
}

// ============================================================================
// Kernel 3: persistent recurrence. 148 CTAs (1/SM), bf16 weights in SMEM.
// ============================================================================
__device__ __forceinline__ float sigmoid_f(float z)
{
    return 1.f / (1.f + __expf(-z));
}
__device__ __forceinline__ float tanh_f(float z)
{
    const float e = __expf(2.f * z);
    return 1.f - __fdividef(2.f, 1.f + e);
}

__global__ void __launch_bounds__(NTHREADS, 1) lstm_recur_kernel(const int* __restrict__ x)
{
    extern __shared__ char smem_raw[];
    float*  __restrict__ h_sm = (float*)(smem_raw + MAX_SMEM_DOTS * HID * 2);
    float4* __restrict__ h4   = (float4*)h_sm;

    const int cta  = blockIdx.x;
    const int tid  = threadIdx.x;
    const int lane = tid & 31;
    const int w    = tid >> 5;

    // unit partition: first 124 CTAs own 14 units, last 24 own 13 (124*14+24*13 = 2048)
    const int nu = (cta < 124) ? 14 : 13;
    const int u0 = (cta < 124) ? cta * 14 : 1736 + (cta - 124) * 13;
    const int nd = nu * 4;
    const int nds = (nd < MAX_SMEM_DOTS) ? nd : MAX_SMEM_DOTS;

    // stage this CTA's weight block (contiguous rows in d_Uh) into SMEM
    {
        const uint4* __restrict__ src = (const uint4*)(d_Uh + (size_t)u0 * 4 * HID);
        uint4* __restrict__ dst = (uint4*)smem_raw;
        const int n = nds * (HID / 8);
        for (int i = tid; i < n; i += NTHREADS) dst[i] = src[i];
    }
    for (int i = tid; i < HID; i += NTHREADS) h_sm[i] = 0.f;

    // per-warp setup: units 2w, 2w+1 -> dot rows (unit*4 + gate), as uint2 (4 bf16 each)
    const int lu0 = 2 * w;
    const int myu = (lu0 + 1 < nu) ? 2 : ((lu0 < nu) ? 1 : 0);
    const uint2* pw[8];
    #pragma unroll
    for (int d = 0; d < 8; d++) pw[d] = (const uint2*)smem_raw;  // safe default
    for (int uu = 0; uu < myu; uu++) {
        for (int g = 0; g < 4; g++) {
            const int ld = (lu0 + uu) * 4 + g;
            if (ld < nds)
                pw[uu * 4 + g] = (const uint2*)(smem_raw + (size_t)ld * HID * 2);
            else
                pw[uu * 4 + g] = (const uint2*)(d_Uh + ((size_t)(u0 + lu0 + uu) * 4 + g) * HID);
        }
    }

    float cst0 = 0.f, cst1 = 0.f;
    unsigned mygen = 0;
    if (tid == 0) mygen = *((volatile unsigned*)&d_bargen);
    __syncthreads();

    for (int t = 0; t < SEQ; t++) {
        // prefetch gate-table row (L2 latency hidden under the dot loop)
        float4 gz0 = make_float4(0.f, 0.f, 0.f, 0.f);
        float4 gz1 = make_float4(0.f, 0.f, 0.f, 0.f);
        if (myu) {
            const int xt = __ldg(&x[t]);
            const float4* Gp = ((const float4*)d_G) + (size_t)xt * HID + (u0 + lu0);
            gz0 = __ldg(&Gp[0]);
            if (myu == 2) gz1 = __ldg(&Gp[1]);
        }

        // dots: z[d] = h . U_row(d). 16 iters x (1 LDS.128 h + 8 LDS.64 w), conflict-free.
        float2 a[8];
        #pragma unroll
        for (int d = 0; d < 8; d++) a[d] = make_float2(0.f, 0.f);

        if (myu == 2) {
            #pragma unroll 4
            for (int ii = 0; ii < 16; ii++) {
                const int i = lane + (ii << 5);        // uint2 index (k = 4i)
                const float4 hv = h4[i];
                #pragma unroll
                for (int d = 0; d < 8; d++) {
                    const uint2 wv = pw[d][i];
                    a[d].x = fmaf(hv.x, bf_lo(wv.x), a[d].x);
                    a[d].y = fmaf(hv.y, bf_hi(wv.x), a[d].y);
                    a[d].x = fmaf(hv.z, bf_lo(wv.y), a[d].x);
                    a[d].y = fmaf(hv.w, bf_hi(wv.y), a[d].y);
                }
            }
        } else if (myu == 1) {
            #pragma unroll 4
            for (int ii = 0; ii < 16; ii++) {
                const int i = lane + (ii << 5);
                const float4 hv = h4[i];
                #pragma unroll
                for (int d = 0; d < 4; d++) {
                    const uint2 wv = pw[d][i];
                    a[d].x = fmaf(hv.x, bf_lo(wv.x), a[d].x);
                    a[d].y = fmaf(hv.y, bf_hi(wv.x), a[d].y);
                    a[d].x = fmaf(hv.z, bf_lo(wv.y), a[d].x);
                    a[d].y = fmaf(hv.w, bf_hi(wv.y), a[d].y);
                }
            }
        }

        float z[8];
        #pragma unroll
        for (int d = 0; d < 8; d++) z[d] = a[d].x + a[d].y;
        #pragma unroll
        for (int d = 0; d < 8; d++) {
            float s = z[d];
            #pragma unroll
            for (int off = 16; off > 0; off >>= 1)
                s += __shfl_xor_sync(0xffffffffu, s, off);
            z[d] = s;
        }

        // gates + cell update (replicated across lanes; lane 0 stores)
        if (myu) {
            {
                const float ig = sigmoid_f(z[0] + gz0.x);
                const float fg = sigmoid_f(z[1] + gz0.y);
                const float gg = tanh_f   (z[2] + gz0.z);
                const float og = sigmoid_f(z[3] + gz0.w);
                const float cn = fg * cst0 + ig * gg;
                cst0 = cn;
                const float hn = og * tanh_f(cn);
                if (lane == 0) {
                    const int j = u0 + lu0;
                    d_hbuf[t & 1][j] = hn;
                    d_hs[(size_t)t * HID + j] = hn;
                    if (t == SEQ - 1) d_cfinal[j] = cn;
                }
            }
            if (myu == 2) {
                const float ig = sigmoid_f(z[4] + gz1.x);
                const float fg = sigmoid_f(z[5] + gz1.y);
                const float gg = tanh_f   (z[6] + gz1.z);
                const float og = sigmoid_f(z[7] + gz1.w);
                const float cn = fg * cst1 + ig * gg;
                cst1 = cn;
                const float hn = og * tanh_f(cn);
                if (lane == 0) {
                    const int j = u0 + lu0 + 1;
                    d_hbuf[t & 1][j] = hn;
                    d_hs[(size_t)t * HID + j] = hn;
                    if (t == SEQ - 1) d_cfinal[j] = cn;
                }
            }
        }

        // grid barrier: single gpu-fence per CTA, acquire-spin on generation
        __syncthreads();
        if (tid == 0) {
            __threadfence();   // publish this CTA's h stores gpu-wide
            const unsigned ticket = atomicAdd(&d_barcnt, 1u);
            if (ticket == gridDim.x - 1) {
                d_barcnt = 0;
                __threadfence();
                atomicAdd(&d_bargen, 1u);
            } else {
                unsigned g;
                do {
                    asm volatile("ld.acquire.gpu.global.u32 %0, [%1];"
                                 : "=r"(g) : "l"(&d_bargen) : "memory");
                } while (g == mygen);
            }
            mygen++;
        }
        __syncthreads();

        // gather the full new h into SMEM (L2, bypass L1)
        {
            float4* __restrict__ dst4 = (float4*)h_sm;
            const float4* __restrict__ s4 = (const float4*)d_hbuf[t & 1];
            for (int i = tid; i < HID / 4; i += NTHREADS)
                dst4[i] = __ldcg(&s4[i]);
        }
        __syncthreads();
    }
}

// ============================================================================
// Kernel 4: out = hs @ V_w + V_b   (8192x2048 @ 2048x256)
// ============================================================================
__global__ void __launch_bounds__(256) out_gemm_kernel(const float* __restrict__ Vw,
                                                       const float* __restrict__ Vb,
                                                       float* __restrict__ out)
{
    __shared__ float As[16][64];
    __shared__ float Bs[16][64];
    const int tid = threadIdx.x;
    const int tx = tid & 15, ty = tid >> 4;
    const int m0 = blockIdx.x * 64, n0 = blockIdx.y * 64;

    float acc[4][4];
    #pragma unroll
    for (int i = 0; i < 4; i++)
        #pragma unroll
        for (int j = 0; j < 4; j++) acc[i][j] = 0.f;

    const int ar = tid >> 2, ac = (tid & 3) * 4;
    const int br = tid >> 4, bc = (tid & 15) * 4;

    for (int k0 = 0; k0 < HID; k0 += 16) {
        const float4 av = *(const float4*)&d_hs[(size_t)(m0 + ar) * HID + k0 + ac];
        As[ac + 0][ar] = av.x; As[ac + 1][ar] = av.y;
        As[ac + 2][ar] = av.z; As[ac + 3][ar] = av.w;
        *(float4*)&Bs[br][bc] = *(const float4*)&Vw[(size_t)(k0 + br) * OUTN + n0 + bc];
        __syncthreads();
        #pragma unroll
        for (int kk = 0; kk < 16; kk++) {
            float a4[4], b4[4];
            *(float4*)a4 = *(const float4*)&As[kk][ty * 4];
            *(float4*)b4 = *(const float4*)&Bs[kk][tx * 4];
            #pragma unroll
            for (int i = 0; i < 4; i++)
                #pragma unroll
                for (int j = 0; j < 4; j++)
                    acc[i][j] = fmaf(a4[i], b4[j], acc[i][j]);
        }
        __syncthreads();
    }
    #pragma unroll
    for (int i = 0; i < 4; i++) {
        #pragma unroll
        for (int j = 0; j < 4; j++) {
            const int oo = n0 + tx * 4 + j;
            out[(size_t)(m0 + ty * 4 + i) * OUTN + oo] = acc[i][j] + Vb[oo];
        }
    }
}

// ============================================================================
// Kernel 5: optional tail (h_T, c_T) if harness expects them appended
// ============================================================================
__global__ void tail_copy_kernel(float* __restrict__ out)
{
    const int i = blockIdx.x * blockDim.x + threadIdx.x;
    if (i < HID) {
        out[(size_t)SEQ * OUTN + i]       = d_hbuf[(SEQ - 1) & 1][i];
        out[(size_t)SEQ * OUTN + HID + i] = d_cfinal[i];
    }
}

// ============================================================================
// host launcher
// inputs: 0:x 1:emb 2:W_i 3:b_i 4:U_i 5:c_i 6:W_f 7:b_f 8:U_f 9:c_f
//         10:W_g 11:b_g 12:U_g 13:c_g 14:W_o 15:b_o 16:U_o 17:c_o 18:V_w 19:V_b
// ============================================================================
extern "C" void kernel_launch(void* const* d_in, const int* in_sizes, int n_in,
                              void* d_out, int out_size)
{
    const int*   x   = (const int*)d_in[0];
    const float* emb = (const float*)d_in[1];

    GateArgs ga;
    UArgs ua;
    ga.W[0] = (const float*)d_in[2];  ga.b[0] = (const float*)d_in[3];
    ua.U[0] = (const float*)d_in[4];  ga.cb[0] = (const float*)d_in[5];
    ga.W[1] = (const float*)d_in[6];  ga.b[1] = (const float*)d_in[7];
    ua.U[1] = (const float*)d_in[8];  ga.cb[1] = (const float*)d_in[9];
    ga.W[2] = (const float*)d_in[10]; ga.b[2] = (const float*)d_in[11];
    ua.U[2] = (const float*)d_in[12]; ga.cb[2] = (const float*)d_in[13];
    ga.W[3] = (const float*)d_in[14]; ga.b[3] = (const float*)d_in[15];
    ua.U[3] = (const float*)d_in[16]; ga.cb[3] = (const float*)d_in[17];
    const float* Vw = (const float*)d_in[18];
    const float* Vb = (const float*)d_in[19];
    float* out = (float*)d_out;

    cudaFuncSetAttribute(lstm_recur_kernel,
                         cudaFuncAttributeMaxDynamicSharedMemorySize, SMEM_RECUR);

    prep_tables_kernel<<<dim3(VOCAB / 8, 4), 256>>>(emb, ga);
    prep_weights_kernel<<<dim3(HID / 32, HID / 32, 4), dim3(32, 32)>>>(ua);
    lstm_recur_kernel<<<NCTA, NTHREADS, SMEM_RECUR>>>(x);
    out_gemm_kernel<<<dim3(SEQ / 64, OUTN / 64), 256>>>(Vw, Vb, out);
    if (out_size >= SEQ * OUTN + 2 * HID)
        tail_copy_kernel<<<(HID + 255) / 256, 256>>>(out);
}